// round 6
// baseline (speedup 1.0000x reference)
#include <cuda_runtime.h>
#include <math.h>

#define N_NODES 100000
#define E_EDGES 1600000
// HID = 64, IN = 128, HEADS = 2

// ---------------- scratch (device globals; no allocations allowed) ----------
__device__ float g_dinv[N_NODES];              // deg -> dinv (in place)
__device__ float g_h[N_NODES * 64];            // x @ gcn_w
__device__ float g_acc[N_NODES * 64];          // GCN accumulator (pre-bias/relu)
__device__ float g_h2[N_NODES * 128];          // hg @ gat_w  [N, 2 heads, 64]
__device__ float g_ss[N_NODES * 2];            // score_src per (node, head)
__device__ float g_sd[N_NODES * 2];            // score_dst per (node, head)
__device__ float g_denom[N_NODES * 2];         // softmax denominator (no max shift)
__device__ float g_out_acc[N_NODES * 64];      // GAT accumulator (head-mean folded)

// ---------------- helpers ----------------------------------------------------
__device__ __forceinline__ void red_add_v4(float* addr, float4 v) {
    asm volatile("red.global.add.v4.f32 [%0], {%1, %2, %3, %4};"
                 :: "l"(addr), "f"(v.x), "f"(v.y), "f"(v.z), "f"(v.w)
                 : "memory");
}
__device__ __forceinline__ float leaky(float a) {
    return a >= 0.f ? a : 0.2f * a;
}
__device__ __forceinline__ float elem4(float4 v, int kk) {
    return (kk == 0) ? v.x : (kk == 1) ? v.y : (kk == 2) ? v.z : v.w;
}

// ---------------- degree / norm ----------------------------------------------
__global__ void k_deg_init() {
    int t = blockIdx.x * blockDim.x + threadIdx.x;
    if (t < N_NODES) g_dinv[t] = 1.0f;   // self-loop weight 1
}
__global__ void k_deg_edges(const int* __restrict__ dst, const float* __restrict__ ew) {
    int e = blockIdx.x * blockDim.x + threadIdx.x;
    if (e < E_EDGES) atomicAdd(&g_dinv[dst[e]], ew[e]);
}
__global__ void k_dinv() {
    int t = blockIdx.x * blockDim.x + threadIdx.x;
    if (t < N_NODES) g_dinv[t] = rsqrtf(g_dinv[t]);   // deg >= 1 always
}

// ---------------- GEMM1: g_h = x[N,128] @ gcn_w[128,64]  (+ gcn self fold) ---
// Broadcast layout: 1 node per thread, 64 cols in registers. Every W LDS.128
// is warp-uniform (broadcast = 1 wavefront) -> FFMA-bound, not L1-bound.
// Epilogue writes g_h and g_acc = dinv^2 * h (GCN self-loop term).
__global__ void __launch_bounds__(128, 5)
k_gemm1(const float* __restrict__ x, const float* __restrict__ W) {
    __shared__ float Ws[128 * 64];
    int tid = threadIdx.x;
#pragma unroll
    for (int i = 0; i < 16; i++) {
        int idx = (i * 128 + tid) * 4;
        *(float4*)&Ws[idx] = *(const float4*)&W[idx];
    }
    __syncthreads();

    int node = blockIdx.x * 128 + tid;
    bool valid = node < N_NODES;
    int nc = valid ? node : N_NODES - 1;
    const float4* xr = (const float4*)(x + (size_t)nc * 128);

    float acc[64];
#pragma unroll
    for (int j = 0; j < 64; j++) acc[j] = 0.f;

    float4 xv = __ldg(&xr[0]);
#pragma unroll 1
    for (int k4 = 0; k4 < 32; k4++) {
        float4 xc = xv;
        if (k4 < 31) xv = __ldg(&xr[k4 + 1]);
#pragma unroll
        for (int kk = 0; kk < 4; kk++) {
            float xs = elem4(xc, kk);
            const float* wr = &Ws[(k4 * 4 + kk) * 64];
#pragma unroll
            for (int j4 = 0; j4 < 16; j4++) {
                float4 w = *(const float4*)&wr[j4 * 4];
                acc[j4 * 4 + 0] += xs * w.x;
                acc[j4 * 4 + 1] += xs * w.y;
                acc[j4 * 4 + 2] += xs * w.z;
                acc[j4 * 4 + 3] += xs * w.w;
            }
        }
    }
    if (valid) {
        float di = g_dinv[node];
        float c = di * di;
        float* hout = &g_h[(size_t)node * 64];
        float* aout = &g_acc[(size_t)node * 64];
#pragma unroll
        for (int j4 = 0; j4 < 16; j4++) {
            float4 v = make_float4(acc[j4 * 4], acc[j4 * 4 + 1],
                                   acc[j4 * 4 + 2], acc[j4 * 4 + 3]);
            *(float4*)&hout[j4 * 4] = v;
            *(float4*)&aout[j4 * 4] = make_float4(c * v.x, c * v.y, c * v.z, c * v.w);
        }
    }
}

// ---------------- GCN edge aggregation ---------------------------------------
__global__ void k_gcn_edges(const int* __restrict__ src, const int* __restrict__ dst,
                            const float* __restrict__ ew) {
    int g = blockIdx.x * blockDim.x + threadIdx.x;
    int e = g >> 4;
    if (e >= E_EDGES) return;
    int t = threadIdx.x & 15;
    int s = __ldg(&src[e]);
    int d = __ldg(&dst[e]);
    float norm = 0.f;
    if (t == 0) norm = g_dinv[s] * __ldg(&ew[e]) * g_dinv[d];
    norm = __shfl_sync(0xffffffffu, norm, 0, 16);
    float4 h = *(const float4*)&g_h[(size_t)s * 64 + t * 4];
    red_add_v4(&g_acc[(size_t)d * 64 + t * 4],
               make_float4(norm * h.x, norm * h.y, norm * h.z, norm * h.w));
}

// ---------------- GEMM2: g_h2 = relu(g_acc + gcn_b) @ gat_w[64,128] ----------
// 2 lanes per node (even: head0 cols 0-63, odd: head1 cols 64-127).
// W smem rows padded: row stride 136 floats, half offset 68 -> even/odd lanes
// hit disjoint banks, every LDS.128 = 1 wavefront.
// Input load folds gcn bias + relu (removes k_gcn_final).
// Epilogue: per-thread full attention dot products (no shfl) + denom init.
__global__ void __launch_bounds__(128, 5)
k_gemm2(const float* __restrict__ W, const float* __restrict__ as_,
        const float* __restrict__ ad_, const float* __restrict__ gb) {
    __shared__ float Ws[64 * 136];
    int tid = threadIdx.x;
#pragma unroll
    for (int i = 0; i < 16; i++) {
        int g = i * 128 + tid;          // float4 id 0..2047
        int k = g >> 5;                 // 32 float4 per 128-col row
        int rem = g & 31;
        int hh = rem >> 4, j4 = rem & 15;
        float4 v = *(const float4*)&W[g * 4];
        *(float4*)&Ws[k * 136 + hh * 68 + j4 * 4] = v;
    }
    __syncthreads();

    int half = tid & 1;
    int node = blockIdx.x * 64 + (tid >> 1);
    bool valid = node < N_NODES;
    int nc = valid ? node : N_NODES - 1;
    const float4* xr = (const float4*)(g_acc + (size_t)nc * 64);

    float acc[64];
#pragma unroll
    for (int j = 0; j < 64; j++) acc[j] = 0.f;

    // prefetch + bias/relu fold
    float4 xv;
    {
        float4 raw = __ldg(&xr[0]);
        float4 bv = __ldg((const float4*)&gb[0]);
        xv = make_float4(fmaxf(raw.x + bv.x, 0.f), fmaxf(raw.y + bv.y, 0.f),
                         fmaxf(raw.z + bv.z, 0.f), fmaxf(raw.w + bv.w, 0.f));
    }
#pragma unroll 1
    for (int k4 = 0; k4 < 16; k4++) {
        float4 xc = xv;
        if (k4 < 15) {
            float4 raw = __ldg(&xr[k4 + 1]);
            float4 bv = __ldg((const float4*)&gb[(k4 + 1) * 4]);
            xv = make_float4(fmaxf(raw.x + bv.x, 0.f), fmaxf(raw.y + bv.y, 0.f),
                             fmaxf(raw.z + bv.z, 0.f), fmaxf(raw.w + bv.w, 0.f));
        }
#pragma unroll
        for (int kk = 0; kk < 4; kk++) {
            float xs = elem4(xc, kk);
            const float* wr = &Ws[(k4 * 4 + kk) * 136 + half * 68];
#pragma unroll
            for (int j4 = 0; j4 < 16; j4++) {
                float4 w = *(const float4*)&wr[j4 * 4];
                acc[j4 * 4 + 0] += xs * w.x;
                acc[j4 * 4 + 1] += xs * w.y;
                acc[j4 * 4 + 2] += xs * w.z;
                acc[j4 * 4 + 3] += xs * w.w;
            }
        }
    }
    if (valid) {
        float* hout = &g_h2[(size_t)node * 128 + half * 64];
#pragma unroll
        for (int j4 = 0; j4 < 16; j4++)
            *(float4*)&hout[j4 * 4] = make_float4(acc[j4 * 4], acc[j4 * 4 + 1],
                                                  acc[j4 * 4 + 2], acc[j4 * 4 + 3]);
        float ps = 0.f, pd = 0.f;
#pragma unroll
        for (int j4 = 0; j4 < 16; j4++) {
            float4 a = __ldg((const float4*)&as_[half * 64 + j4 * 4]);
            float4 d = __ldg((const float4*)&ad_[half * 64 + j4 * 4]);
            ps += acc[j4 * 4] * a.x + acc[j4 * 4 + 1] * a.y
                + acc[j4 * 4 + 2] * a.z + acc[j4 * 4 + 3] * a.w;
            pd += acc[j4 * 4] * d.x + acc[j4 * 4 + 1] * d.y
                + acc[j4 * 4 + 2] * d.z + acc[j4 * 4 + 3] * d.w;
        }
        g_ss[2 * node + half] = ps;
        g_sd[2 * node + half] = pd;
        g_denom[2 * node + half] = expf(leaky(ps + pd));   // self-loop term
    }
}

// ---------------- softmax denominator over edges ------------------------------
__global__ void k_denom_edges(const int* __restrict__ src, const int* __restrict__ dst) {
    int g = blockIdx.x * blockDim.x + threadIdx.x;
    if (g >= 2 * E_EDGES) return;
    int e = g >> 1, h = g & 1;
    int s = __ldg(&src[e]);
    int d = __ldg(&dst[e]);
    float a = leaky(g_ss[2 * s + h] + g_sd[2 * d + h]);
    atomicAdd(&g_denom[2 * d + h], expf(a));
}

// ---------------- GAT aggregation (head-mean folded: 64-wide accumulator) ----
__global__ void k_gat_self() {
    int t = blockIdx.x * blockDim.x + threadIdx.x;
    if (t >= N_NODES * 16) return;
    int n = t >> 4, q = t & 15;
    float ex0 = expf(leaky(g_ss[2 * n] + g_sd[2 * n]));
    float ex1 = expf(leaky(g_ss[2 * n + 1] + g_sd[2 * n + 1]));
    float c0 = ex0 / fmaxf(g_denom[2 * n], 1e-16f);
    float c1 = ex1 / fmaxf(g_denom[2 * n + 1], 1e-16f);
    const float* hr = &g_h2[(size_t)n * 128];
    float4 f0 = *(const float4*)&hr[q * 4];
    float4 f1 = *(const float4*)&hr[64 + q * 4];
    *(float4*)&g_out_acc[(size_t)n * 64 + q * 4] =
        make_float4(0.5f * (c0 * f0.x + c1 * f1.x),
                    0.5f * (c0 * f0.y + c1 * f1.y),
                    0.5f * (c0 * f0.z + c1 * f1.z),
                    0.5f * (c0 * f0.w + c1 * f1.w));
}

__global__ void k_gat_edges(const int* __restrict__ src, const int* __restrict__ dst) {
    int g = blockIdx.x * blockDim.x + threadIdx.x;
    int e = g >> 4;
    if (e >= E_EDGES) return;
    int t = threadIdx.x & 15;
    int s = __ldg(&src[e]);
    int d = __ldg(&dst[e]);
    float coef = 0.f;
    if (t < 2) {
        float a = leaky(g_ss[2 * s + t] + g_sd[2 * d + t]);
        coef = expf(a) / fmaxf(g_denom[2 * d + t], 1e-16f);
    }
    float c0 = __shfl_sync(0xffffffffu, coef, 0, 16);
    float c1 = __shfl_sync(0xffffffffu, coef, 1, 16);
    const float* hr = &g_h2[(size_t)s * 128];
    float4 f0 = *(const float4*)&hr[t * 4];
    float4 f1 = *(const float4*)&hr[64 + t * 4];
    red_add_v4(&g_out_acc[(size_t)d * 64 + t * 4],
               make_float4(0.5f * (c0 * f0.x + c1 * f1.x),
                           0.5f * (c0 * f0.y + c1 * f1.y),
                           0.5f * (c0 * f0.z + c1 * f1.z),
                           0.5f * (c0 * f0.w + c1 * f1.w)));
}

__global__ void k_final(const float* __restrict__ b, float* __restrict__ out) {
    int t = blockIdx.x * blockDim.x + threadIdx.x;
    if (t >= N_NODES * 16) return;
    int q = t & 15;
    float4 a = *(const float4*)&g_out_acc[(size_t)t * 4];
    float4 bv = *(const float4*)&b[q * 4];
    *(float4*)&out[(size_t)t * 4] =
        make_float4(fmaxf(a.x + bv.x, 0.f), fmaxf(a.y + bv.y, 0.f),
                    fmaxf(a.z + bv.z, 0.f), fmaxf(a.w + bv.w, 0.f));
}

// ---------------- launch -----------------------------------------------------
extern "C" void kernel_launch(void* const* d_in, const int* in_sizes, int n_in,
                              void* d_out, int out_size) {
    const float* x       = (const float*)d_in[0];
    const int*   ei      = (const int*)d_in[1];
    const float* ew      = (const float*)d_in[2];
    const float* gcn_w   = (const float*)d_in[3];
    const float* gcn_b   = (const float*)d_in[4];
    const float* gat_w   = (const float*)d_in[5];
    const float* att_src = (const float*)d_in[6];
    const float* att_dst = (const float*)d_in[7];
    const float* gat_b   = (const float*)d_in[8];
    float* out = (float*)d_out;
    const int* src = ei;
    const int* dst = ei + E_EDGES;

    const int B = 256;
    // degrees / normalization (needed by gemm1 epilogue)
    k_deg_init<<<(N_NODES + B - 1) / B, B>>>();
    k_deg_edges<<<(E_EDGES + B - 1) / B, B>>>(dst, ew);
    k_dinv<<<(N_NODES + B - 1) / B, B>>>();
    // GCN
    k_gemm1<<<(N_NODES + 127) / 128, 128>>>(x, gcn_w);
    k_gcn_edges<<<(E_EDGES * 16 + B - 1) / B, B>>>(src, dst, ew);
    // GAT (gemm2 folds gcn bias+relu on input load)
    k_gemm2<<<(N_NODES + 63) / 64, 128>>>(gat_w, att_src, att_dst, gcn_b);
    k_denom_edges<<<(2 * E_EDGES + B - 1) / B, B>>>(src, dst);
    k_gat_self<<<(N_NODES * 16 + B - 1) / B, B>>>();
    k_gat_edges<<<(E_EDGES * 16 + B - 1) / B, B>>>(src, dst);
    k_final<<<(N_NODES * 16 + B - 1) / B, B>>>(gat_b, out);
}

// round 8
// speedup vs baseline: 1.0607x; 1.0607x over previous
#include <cuda_runtime.h>
#include <math.h>

#define N_NODES 100000
#define E_EDGES 1600000
// HID = 64, IN = 128, HEADS = 2

// ---------------- scratch (device globals; no allocations allowed) ----------
__device__ float g_dinv[N_NODES];              // deg -> dinv (in place)
__device__ float g_h[N_NODES * 64];            // x @ gcn_w
__device__ float g_acc[N_NODES * 64];          // GCN accumulator (pre-bias/relu)
__device__ float g_h2[N_NODES * 128];          // hg @ gat_w  [N, 2 heads, 64]
__device__ float g_ss[N_NODES * 2];            // score_src per (node, head)
__device__ float g_sd[N_NODES * 2];            // score_dst per (node, head)
__device__ float g_denom[N_NODES * 2];         // softmax denominator (no max shift)
__device__ float g_out_acc[N_NODES * 64];      // GAT accumulator (head-mean folded)

// ---------------- helpers ----------------------------------------------------
__device__ __forceinline__ void red_add_v4(float* addr, float4 v) {
    asm volatile("red.global.add.v4.f32 [%0], {%1, %2, %3, %4};"
                 :: "l"(addr), "f"(v.x), "f"(v.y), "f"(v.z), "f"(v.w)
                 : "memory");
}
__device__ __forceinline__ float leaky(float a) {
    return a >= 0.f ? a : 0.2f * a;
}

// ---------------- degree / norm ----------------------------------------------
__global__ void k_deg_init() {
    int t = blockIdx.x * blockDim.x + threadIdx.x;
    if (t < N_NODES) g_dinv[t] = 1.0f;   // self-loop weight 1
}
__global__ void k_deg_edges(const int* __restrict__ dst, const float* __restrict__ ew) {
    int e = blockIdx.x * blockDim.x + threadIdx.x;
    if (e < E_EDGES) atomicAdd(&g_dinv[dst[e]], ew[e]);
}
__global__ void k_dinv() {
    int t = blockIdx.x * blockDim.x + threadIdx.x;
    if (t < N_NODES) g_dinv[t] = rsqrtf(g_dinv[t]);   // deg >= 1 always
}

// ---------------- GEMM1: g_h = x[N,128] @ gcn_w[128,64]  (+ gcn self fold) ---
// 1 node/thread, 64 cols in regs. W smem reads are warp-broadcast (1 wf/LDS).
// x staged through smem in 16-col chunks: coalesced LDG + stride-17 scalar LDS
// (odd stride -> bank permutation, conflict-free). Total smem 40.9 KB.
__global__ void __launch_bounds__(128, 4)
k_gemm1(const float* __restrict__ x, const float* __restrict__ W) {
    __shared__ float Ws[128 * 64];     // 32 KB
    __shared__ float Xs[128 * 17];     // 8.7 KB
    int tid = threadIdx.x;
#pragma unroll
    for (int i = 0; i < 16; i++) {
        int idx = (i * 128 + tid) * 4;
        *(float4*)&Ws[idx] = __ldg((const float4*)&W[idx]);
    }

    int node = blockIdx.x * 128 + tid;
    bool valid = node < N_NODES;

    float acc[64];
#pragma unroll
    for (int j = 0; j < 64; j++) acc[j] = 0.f;

#pragma unroll 1
    for (int kc = 0; kc < 8; kc++) {
        __syncthreads();
        // stage x[block nodes, kc*16 .. kc*16+16): 512 float4, coalesced
#pragma unroll
        for (int i = 0; i < 4; i++) {
            int g = i * 128 + tid;
            int n = g >> 2;            // node row in tile (0..127)
            int c4 = g & 3;            // float4 within 16-col chunk
            int gn = blockIdx.x * 128 + n;
            if (gn >= N_NODES) gn = N_NODES - 1;
            float4 v = __ldg((const float4*)&x[(size_t)gn * 128 + kc * 16 + c4 * 4]);
            float* dp = &Xs[n * 17 + c4 * 4];
            dp[0] = v.x; dp[1] = v.y; dp[2] = v.z; dp[3] = v.w;
        }
        __syncthreads();
#pragma unroll 1
        for (int k = 0; k < 16; k++) {
            float xs = Xs[tid * 17 + k];            // conflict-free (odd stride)
            const float* wr = &Ws[(kc * 16 + k) * 64];
#pragma unroll
            for (int j4 = 0; j4 < 16; j4++) {
                float4 w = *(const float4*)&wr[j4 * 4];   // warp-broadcast
                acc[j4 * 4 + 0] += xs * w.x;
                acc[j4 * 4 + 1] += xs * w.y;
                acc[j4 * 4 + 2] += xs * w.z;
                acc[j4 * 4 + 3] += xs * w.w;
            }
        }
    }
    if (valid) {
        float di = g_dinv[node];
        float c = di * di;
        float* hout = &g_h[(size_t)node * 64];
        float* aout = &g_acc[(size_t)node * 64];
#pragma unroll
        for (int j4 = 0; j4 < 16; j4++) {
            float4 v = make_float4(acc[j4 * 4], acc[j4 * 4 + 1],
                                   acc[j4 * 4 + 2], acc[j4 * 4 + 3]);
            *(float4*)&hout[j4 * 4] = v;
            *(float4*)&aout[j4 * 4] = make_float4(c * v.x, c * v.y, c * v.z, c * v.w);
        }
    }
}

// ---------------- GCN edge aggregation ---------------------------------------
__global__ void k_gcn_edges(const int* __restrict__ src, const int* __restrict__ dst,
                            const float* __restrict__ ew) {
    int g = blockIdx.x * blockDim.x + threadIdx.x;
    int e = g >> 4;
    if (e >= E_EDGES) return;
    int t = threadIdx.x & 15;
    int s = __ldg(&src[e]);
    int d = __ldg(&dst[e]);
    float norm = 0.f;
    if (t == 0) norm = g_dinv[s] * __ldg(&ew[e]) * g_dinv[d];
    norm = __shfl_sync(0xffffffffu, norm, 0, 16);
    float4 h = *(const float4*)&g_h[(size_t)s * 64 + t * 4];
    red_add_v4(&g_acc[(size_t)d * 64 + t * 4],
               make_float4(norm * h.x, norm * h.y, norm * h.z, norm * h.w));
}

// ---------------- GEMM2: g_h2 = relu(g_acc + gcn_b) @ gat_w[64,128] ----------
// 2 lanes/node (even: head0 cols 0-63, odd: head1 cols 64-127). W rows padded
// (stride 136, half-offset 68) -> the 2 distinct LDS addrs/warp land on
// different banks, 1 wf/LDS. hg staged in 2 chunks of 32 cols (stride 33,
// bias+relu folded; 16-bank / 2-lane-broadcast reads, conflict-free).
// smem total 43.2 KB. Epilogue: h2 store + per-thread attn dots + denom init.
__global__ void __launch_bounds__(128, 4)
k_gemm2(const float* __restrict__ W, const float* __restrict__ as_,
        const float* __restrict__ ad_, const float* __restrict__ gb) {
    __shared__ float Ws[64 * 136];    // 34.8 KB
    __shared__ float Xs[64 * 33];     // 8.4 KB (rows of 32 floats!)
    int tid = threadIdx.x;
#pragma unroll
    for (int i = 0; i < 16; i++) {
        int g = i * 128 + tid;          // float4 id 0..2047
        int k = g >> 5;                 // 32 float4 per 128-col row
        int rem = g & 31;
        int hh = rem >> 4, j4 = rem & 15;
        float4 v = __ldg((const float4*)&W[g * 4]);
        *(float4*)&Ws[k * 136 + hh * 68 + j4 * 4] = v;
    }

    int half = tid & 1;
    int nl = tid >> 1;                  // node within tile (0..63)
    int node = blockIdx.x * 64 + nl;
    bool valid = node < N_NODES;

    float acc[64];
#pragma unroll
    for (int j = 0; j < 64; j++) acc[j] = 0.f;

#pragma unroll 1
    for (int kc = 0; kc < 2; kc++) {
        __syncthreads();
        // stage hg[block nodes, kc*32 .. kc*32+32): 64 x 32 = 512 float4
#pragma unroll
        for (int i = 0; i < 4; i++) {
            int g = i * 128 + tid;
            int n = g >> 3;             // node row (0..63)
            int c4 = g & 7;             // float4 within 32-col chunk
            int gn = blockIdx.x * 64 + n;
            if (gn >= N_NODES) gn = N_NODES - 1;
            float4 raw = __ldg((const float4*)&g_acc[(size_t)gn * 64 + kc * 32 + c4 * 4]);
            float4 bv = __ldg((const float4*)&gb[kc * 32 + c4 * 4]);
            float* dp = &Xs[n * 33 + c4 * 4];
            dp[0] = fmaxf(raw.x + bv.x, 0.f);
            dp[1] = fmaxf(raw.y + bv.y, 0.f);
            dp[2] = fmaxf(raw.z + bv.z, 0.f);
            dp[3] = fmaxf(raw.w + bv.w, 0.f);
        }
        __syncthreads();
#pragma unroll 1
        for (int k = 0; k < 32; k++) {
            float xs = Xs[nl * 33 + k];
            const float* wr = &Ws[(kc * 32 + k) * 136 + half * 68];
#pragma unroll
            for (int j4 = 0; j4 < 16; j4++) {
                float4 w = *(const float4*)&wr[j4 * 4];
                acc[j4 * 4 + 0] += xs * w.x;
                acc[j4 * 4 + 1] += xs * w.y;
                acc[j4 * 4 + 2] += xs * w.z;
                acc[j4 * 4 + 3] += xs * w.w;
            }
        }
    }
    if (valid) {
        float* hout = &g_h2[(size_t)node * 128 + half * 64];
#pragma unroll
        for (int j4 = 0; j4 < 16; j4++)
            *(float4*)&hout[j4 * 4] = make_float4(acc[j4 * 4], acc[j4 * 4 + 1],
                                                  acc[j4 * 4 + 2], acc[j4 * 4 + 3]);
        float ps = 0.f, pd = 0.f;
#pragma unroll
        for (int j4 = 0; j4 < 16; j4++) {
            float4 a = __ldg((const float4*)&as_[half * 64 + j4 * 4]);
            float4 d = __ldg((const float4*)&ad_[half * 64 + j4 * 4]);
            ps += acc[j4 * 4] * a.x + acc[j4 * 4 + 1] * a.y
                + acc[j4 * 4 + 2] * a.z + acc[j4 * 4 + 3] * a.w;
            pd += acc[j4 * 4] * d.x + acc[j4 * 4 + 1] * d.y
                + acc[j4 * 4 + 2] * d.z + acc[j4 * 4 + 3] * d.w;
        }
        g_ss[2 * node + half] = ps;
        g_sd[2 * node + half] = pd;
        g_denom[2 * node + half] = expf(leaky(ps + pd));   // self-loop term
    }
}

// ---------------- softmax denominator over edges ------------------------------
__global__ void k_denom_edges(const int* __restrict__ src, const int* __restrict__ dst) {
    int g = blockIdx.x * blockDim.x + threadIdx.x;
    if (g >= 2 * E_EDGES) return;
    int e = g >> 1, h = g & 1;
    int s = __ldg(&src[e]);
    int d = __ldg(&dst[e]);
    float a = leaky(g_ss[2 * s + h] + g_sd[2 * d + h]);
    atomicAdd(&g_denom[2 * d + h], expf(a));
}

// ---------------- GAT aggregation (head-mean folded: 64-wide accumulator) ----
__global__ void k_gat_self() {
    int t = blockIdx.x * blockDim.x + threadIdx.x;
    if (t >= N_NODES * 16) return;
    int n = t >> 4, q = t & 15;
    float ex0 = expf(leaky(g_ss[2 * n] + g_sd[2 * n]));
    float ex1 = expf(leaky(g_ss[2 * n + 1] + g_sd[2 * n + 1]));
    float c0 = ex0 / fmaxf(g_denom[2 * n], 1e-16f);
    float c1 = ex1 / fmaxf(g_denom[2 * n + 1], 1e-16f);
    const float* hr = &g_h2[(size_t)n * 128];
    float4 f0 = *(const float4*)&hr[q * 4];
    float4 f1 = *(const float4*)&hr[64 + q * 4];
    *(float4*)&g_out_acc[(size_t)n * 64 + q * 4] =
        make_float4(0.5f * (c0 * f0.x + c1 * f1.x),
                    0.5f * (c0 * f0.y + c1 * f1.y),
                    0.5f * (c0 * f0.z + c1 * f1.z),
                    0.5f * (c0 * f0.w + c1 * f1.w));
}

__global__ void k_gat_edges(const int* __restrict__ src, const int* __restrict__ dst) {
    int g = blockIdx.x * blockDim.x + threadIdx.x;
    int e = g >> 4;
    if (e >= E_EDGES) return;
    int t = threadIdx.x & 15;
    int s = __ldg(&src[e]);
    int d = __ldg(&dst[e]);
    float coef = 0.f;
    if (t < 2) {
        float a = leaky(g_ss[2 * s + t] + g_sd[2 * d + t]);
        coef = expf(a) / fmaxf(g_denom[2 * d + t], 1e-16f);
    }
    float c0 = __shfl_sync(0xffffffffu, coef, 0, 16);
    float c1 = __shfl_sync(0xffffffffu, coef, 1, 16);
    const float* hr = &g_h2[(size_t)s * 128];
    float4 f0 = *(const float4*)&hr[t * 4];
    float4 f1 = *(const float4*)&hr[64 + t * 4];
    red_add_v4(&g_out_acc[(size_t)d * 64 + t * 4],
               make_float4(0.5f * (c0 * f0.x + c1 * f1.x),
                           0.5f * (c0 * f0.y + c1 * f1.y),
                           0.5f * (c0 * f0.z + c1 * f1.z),
                           0.5f * (c0 * f0.w + c1 * f1.w)));
}

__global__ void k_final(const float* __restrict__ b, float* __restrict__ out) {
    int t = blockIdx.x * blockDim.x + threadIdx.x;
    if (t >= N_NODES * 16) return;
    int q = t & 15;
    float4 a = *(const float4*)&g_out_acc[(size_t)t * 4];
    float4 bv = *(const float4*)&b[q * 4];
    *(float4*)&out[(size_t)t * 4] =
        make_float4(fmaxf(a.x + bv.x, 0.f), fmaxf(a.y + bv.y, 0.f),
                    fmaxf(a.z + bv.z, 0.f), fmaxf(a.w + bv.w, 0.f));
}

// ---------------- launch -----------------------------------------------------
extern "C" void kernel_launch(void* const* d_in, const int* in_sizes, int n_in,
                              void* d_out, int out_size) {
    const float* x       = (const float*)d_in[0];
    const int*   ei      = (const int*)d_in[1];
    const float* ew      = (const float*)d_in[2];
    const float* gcn_w   = (const float*)d_in[3];
    const float* gcn_b   = (const float*)d_in[4];
    const float* gat_w   = (const float*)d_in[5];
    const float* att_src = (const float*)d_in[6];
    const float* att_dst = (const float*)d_in[7];
    const float* gat_b   = (const float*)d_in[8];
    float* out = (float*)d_out;
    const int* src = ei;
    const int* dst = ei + E_EDGES;

    const int B = 256;
    // degrees / normalization (needed by gemm1 epilogue)
    k_deg_init<<<(N_NODES + B - 1) / B, B>>>();
    k_deg_edges<<<(E_EDGES + B - 1) / B, B>>>(dst, ew);
    k_dinv<<<(N_NODES + B - 1) / B, B>>>();
    // GCN
    k_gemm1<<<(N_NODES + 127) / 128, 128>>>(x, gcn_w);
    k_gcn_edges<<<(E_EDGES * 16 + B - 1) / B, B>>>(src, dst, ew);
    // GAT (gemm2 folds gcn bias+relu on staged input load)
    k_gemm2<<<(N_NODES + 63) / 64, 128>>>(gat_w, att_src, att_dst, gcn_b);
    k_denom_edges<<<(2 * E_EDGES + B - 1) / B, B>>>(src, dst);
    k_gat_self<<<(N_NODES * 16 + B - 1) / B, B>>>();
    k_gat_edges<<<(E_EDGES * 16 + B - 1) / B, B>>>(src, dst);
    k_final<<<(N_NODES * 16 + B - 1) / B, B>>>(gat_b, out);
}

// round 9
// speedup vs baseline: 1.2488x; 1.1774x over previous
#include <cuda_runtime.h>
#include <cuda_fp16.h>
#include <math.h>

#define N_NODES 100000
#define E_EDGES 1600000
// HID = 64, IN = 128, HEADS = 2

// ---------------- scratch (device globals; no allocations allowed) ----------
__device__ float   g_dinv[N_NODES];            // deg -> dinv (in place)
__device__ float   g_h[N_NODES * 64];          // x @ gcn_w
__device__ float   g_acc[N_NODES * 64];        // GCN accumulator (pre-bias/relu)
__device__ __half2 g_h2x[N_NODES * 64];        // h2 packed (head0,head1) per col
__device__ float   g_ss[N_NODES * 2];          // score_src per (node, head)
__device__ float   g_sd[N_NODES * 2];          // score_dst per (node, head)
__device__ float   g_denom[N_NODES * 2];       // softmax denominator (no max shift)
__device__ float   g_out_acc[N_NODES * 64];    // GAT accumulator (head-mean folded)

// ---------------- helpers ----------------------------------------------------
__device__ __forceinline__ void red_add_v4(float* addr, float4 v) {
    asm volatile("red.global.add.v4.f32 [%0], {%1, %2, %3, %4};"
                 :: "l"(addr), "f"(v.x), "f"(v.y), "f"(v.z), "f"(v.w)
                 : "memory");
}
__device__ __forceinline__ void red_add_v2(float* addr, float a, float b) {
    asm volatile("red.global.add.v2.f32 [%0], {%1, %2};"
                 :: "l"(addr), "f"(a), "f"(b)
                 : "memory");
}
__device__ __forceinline__ float leaky(float a) {
    return a >= 0.f ? a : 0.2f * a;
}

// ---------------- degree / norm ----------------------------------------------
__global__ void k_deg_init() {
    int t = blockIdx.x * blockDim.x + threadIdx.x;
    if (t < N_NODES) g_dinv[t] = 1.0f;   // self-loop weight 1
}
__global__ void k_deg_edges(const int* __restrict__ dst, const float* __restrict__ ew) {
    int e = blockIdx.x * blockDim.x + threadIdx.x;
    if (e < E_EDGES) atomicAdd(&g_dinv[dst[e]], ew[e]);
}
__global__ void k_dinv() {
    int t = blockIdx.x * blockDim.x + threadIdx.x;
    if (t < N_NODES) g_dinv[t] = rsqrtf(g_dinv[t]);   // deg >= 1 always
}

// ---------------- GEMM1: g_h = x[N,128] @ gcn_w[128,64]  (+ gcn self fold) ---
// 4 nodes x 8 cols/thread (W float4s cg and cg+8 -> warp LDS spans 128B = 1 wf)
// + X staged through smem (coalesced LDG; stride-17 scalar LDS, conflict-free).
// Block 256 thr = 8 cg x 32 ng(4 nodes) -> 128 nodes/block.
__global__ void k_gemm1(const float* __restrict__ x, const float* __restrict__ W) {
    __shared__ float Ws[128 * 64];     // 32 KB row-major
    __shared__ float Xs[128 * 17];     // 8.7 KB (16-col chunks)
    int tid = threadIdx.x;
    for (int i = tid * 4; i < 128 * 64; i += 256 * 4)
        *(float4*)&Ws[i] = __ldg((const float4*)&W[i]);

    int cg = tid & 7;
    int ng = tid >> 3;                 // 0..31
    int n0 = blockIdx.x * 128 + ng * 4;

    float acc[4][8];
#pragma unroll
    for (int i = 0; i < 4; i++)
#pragma unroll
        for (int j = 0; j < 8; j++) acc[i][j] = 0.f;

#pragma unroll 1
    for (int kc = 0; kc < 8; kc++) {
        __syncthreads();
        // stage x[block nodes, kc*16 .. +16): 128x4 float4, coalesced
#pragma unroll
        for (int it = 0; it < 2; it++) {
            int g = it * 256 + tid;
            int n = g >> 2, c4 = g & 3;
            int gn = blockIdx.x * 128 + n;
            if (gn >= N_NODES) gn = N_NODES - 1;
            float4 v = __ldg((const float4*)&x[(size_t)gn * 128 + kc * 16 + c4 * 4]);
            float* dp = &Xs[n * 17 + c4 * 4];
            dp[0] = v.x; dp[1] = v.y; dp[2] = v.z; dp[3] = v.w;
        }
        __syncthreads();
#pragma unroll 1
        for (int k = 0; k < 16; k++) {
            int kk = kc * 16 + k;
            float4 wa = *(const float4*)&Ws[kk * 64 + cg * 4];        // cols 4cg..
            float4 wb = *(const float4*)&Ws[kk * 64 + 32 + cg * 4];   // cols 32+4cg..
            float xs0 = Xs[(ng * 4 + 0) * 17 + k];
            float xs1 = Xs[(ng * 4 + 1) * 17 + k];
            float xs2 = Xs[(ng * 4 + 2) * 17 + k];
            float xs3 = Xs[(ng * 4 + 3) * 17 + k];
#pragma unroll
            for (int i = 0; i < 4; i++) {
                float xs = (i == 0) ? xs0 : (i == 1) ? xs1 : (i == 2) ? xs2 : xs3;
                acc[i][0] += xs * wa.x; acc[i][1] += xs * wa.y;
                acc[i][2] += xs * wa.z; acc[i][3] += xs * wa.w;
                acc[i][4] += xs * wb.x; acc[i][5] += xs * wb.y;
                acc[i][6] += xs * wb.z; acc[i][7] += xs * wb.w;
            }
        }
    }
#pragma unroll
    for (int i = 0; i < 4; i++) {
        int n = n0 + i;
        if (n >= N_NODES) break;
        float di = g_dinv[n];
        float c = di * di;
        float* hout = &g_h[(size_t)n * 64];
        float* aout = &g_acc[(size_t)n * 64];
        float4 va = make_float4(acc[i][0], acc[i][1], acc[i][2], acc[i][3]);
        float4 vb = make_float4(acc[i][4], acc[i][5], acc[i][6], acc[i][7]);
        *(float4*)&hout[cg * 4]      = va;
        *(float4*)&hout[32 + cg * 4] = vb;
        *(float4*)&aout[cg * 4]      = make_float4(c * va.x, c * va.y, c * va.z, c * va.w);
        *(float4*)&aout[32 + cg * 4] = make_float4(c * vb.x, c * vb.y, c * vb.z, c * vb.w);
    }
}

// ---------------- GCN edge aggregation ---------------------------------------
__global__ void k_gcn_edges(const int* __restrict__ src, const int* __restrict__ dst,
                            const float* __restrict__ ew) {
    int g = blockIdx.x * blockDim.x + threadIdx.x;
    int e = g >> 4;
    if (e >= E_EDGES) return;
    int t = threadIdx.x & 15;
    int s = __ldg(&src[e]);
    int d = __ldg(&dst[e]);
    float norm = 0.f;
    if (t == 0) norm = g_dinv[s] * __ldg(&ew[e]) * g_dinv[d];
    norm = __shfl_sync(0xffffffffu, norm, 0, 16);
    float4 h = *(const float4*)&g_h[(size_t)s * 64 + t * 4];
    red_add_v4(&g_acc[(size_t)d * 64 + t * 4],
               make_float4(norm * h.x, norm * h.y, norm * h.z, norm * h.w));
}

// ---------------- GEMM2: h2 = relu(g_acc + gcn_b) @ gat_w[64,128] ------------
// 4 nodes x 8 cols/thread; thread owns col 4cg.. of head0 (f4 cg) AND head1
// (f4 cg+16) -> packs __half2(h0,h1) directly. X staged (2 chunks of 32,
// stride 33, bias+relu folded). Epilogue: h2x store + shfl-reduced scores +
// denom self-init. Block 256 = 16 cg x 16 ng(4) -> 64 nodes/block.
__global__ void k_gemm2(const float* __restrict__ W, const float* __restrict__ as_,
                        const float* __restrict__ ad_, const float* __restrict__ gb) {
    __shared__ float Ws[64 * 128];    // 32 KB row-major
    __shared__ float Xs[64 * 33];     // 8.4 KB (32-col chunks)
    int tid = threadIdx.x;
    for (int i = tid * 4; i < 64 * 128; i += 256 * 4)
        *(float4*)&Ws[i] = __ldg((const float4*)&W[i]);

    int cg = tid & 15;
    int ng = tid >> 4;                 // 0..15
    int n0 = blockIdx.x * 64 + ng * 4;

    float acc[4][8];
#pragma unroll
    for (int i = 0; i < 4; i++)
#pragma unroll
        for (int j = 0; j < 8; j++) acc[i][j] = 0.f;

#pragma unroll 1
    for (int kc = 0; kc < 2; kc++) {
        __syncthreads();
        // stage relu(g_acc + gb)[block nodes, kc*32 .. +32): 64x8 float4
#pragma unroll
        for (int it = 0; it < 2; it++) {
            int g = it * 256 + tid;
            int n = g >> 3, c4 = g & 7;
            int gn = blockIdx.x * 64 + n;
            if (gn >= N_NODES) gn = N_NODES - 1;
            float4 raw = __ldg((const float4*)&g_acc[(size_t)gn * 64 + kc * 32 + c4 * 4]);
            float4 bv = __ldg((const float4*)&gb[kc * 32 + c4 * 4]);
            float* dp = &Xs[n * 33 + c4 * 4];
            dp[0] = fmaxf(raw.x + bv.x, 0.f);
            dp[1] = fmaxf(raw.y + bv.y, 0.f);
            dp[2] = fmaxf(raw.z + bv.z, 0.f);
            dp[3] = fmaxf(raw.w + bv.w, 0.f);
        }
        __syncthreads();
#pragma unroll 1
        for (int k = 0; k < 32; k++) {
            int kk = kc * 32 + k;
            float4 wa = *(const float4*)&Ws[kk * 128 + cg * 4];       // head0 cols 4cg..
            float4 wb = *(const float4*)&Ws[kk * 128 + 64 + cg * 4];  // head1 cols 4cg..
            float xs0 = Xs[(ng * 4 + 0) * 33 + k];
            float xs1 = Xs[(ng * 4 + 1) * 33 + k];
            float xs2 = Xs[(ng * 4 + 2) * 33 + k];
            float xs3 = Xs[(ng * 4 + 3) * 33 + k];
#pragma unroll
            for (int i = 0; i < 4; i++) {
                float xs = (i == 0) ? xs0 : (i == 1) ? xs1 : (i == 2) ? xs2 : xs3;
                acc[i][0] += xs * wa.x; acc[i][1] += xs * wa.y;
                acc[i][2] += xs * wa.z; acc[i][3] += xs * wa.w;
                acc[i][4] += xs * wb.x; acc[i][5] += xs * wb.y;
                acc[i][6] += xs * wb.z; acc[i][7] += xs * wb.w;
            }
        }
    }
    // att vectors: head0 cols 4cg.., head1 cols 4cg.. (att_* flattened [2,64])
    float4 a0 = __ldg((const float4*)&as_[cg * 4]);
    float4 a1 = __ldg((const float4*)&as_[64 + cg * 4]);
    float4 d0 = __ldg((const float4*)&ad_[cg * 4]);
    float4 d1 = __ldg((const float4*)&ad_[64 + cg * 4]);
#pragma unroll
    for (int i = 0; i < 4; i++) {
        int n = n0 + i;
        bool valid = n < N_NODES;
        if (valid) {
            __half2 p0 = __floats2half2_rn(acc[i][0], acc[i][4]);
            __half2 p1 = __floats2half2_rn(acc[i][1], acc[i][5]);
            __half2 p2 = __floats2half2_rn(acc[i][2], acc[i][6]);
            __half2 p3 = __floats2half2_rn(acc[i][3], acc[i][7]);
            uint4 pk;
            pk.x = *(unsigned*)&p0; pk.y = *(unsigned*)&p1;
            pk.z = *(unsigned*)&p2; pk.w = *(unsigned*)&p3;
            *(uint4*)&g_h2x[(size_t)n * 64 + cg * 4] = pk;
        }
        float ps0 = acc[i][0] * a0.x + acc[i][1] * a0.y + acc[i][2] * a0.z + acc[i][3] * a0.w;
        float pd0 = acc[i][0] * d0.x + acc[i][1] * d0.y + acc[i][2] * d0.z + acc[i][3] * d0.w;
        float ps1 = acc[i][4] * a1.x + acc[i][5] * a1.y + acc[i][6] * a1.z + acc[i][7] * a1.w;
        float pd1 = acc[i][4] * d1.x + acc[i][5] * d1.y + acc[i][6] * d1.z + acc[i][7] * d1.w;
#pragma unroll
        for (int off = 1; off < 16; off <<= 1) {
            ps0 += __shfl_xor_sync(0xffffffffu, ps0, off, 16);
            pd0 += __shfl_xor_sync(0xffffffffu, pd0, off, 16);
            ps1 += __shfl_xor_sync(0xffffffffu, ps1, off, 16);
            pd1 += __shfl_xor_sync(0xffffffffu, pd1, off, 16);
        }
        if (cg == 0 && valid) {
            *(float2*)&g_ss[2 * n] = make_float2(ps0, ps1);
            *(float2*)&g_sd[2 * n] = make_float2(pd0, pd1);
            *(float2*)&g_denom[2 * n] =
                make_float2(expf(leaky(ps0 + pd0)), expf(leaky(ps1 + pd1)));  // self term
        }
    }
}

// ---------------- softmax denominator over edges (1 thr/edge, v2 red) --------
__global__ void k_denom_edges(const int* __restrict__ src, const int* __restrict__ dst) {
    int e = blockIdx.x * blockDim.x + threadIdx.x;
    if (e >= E_EDGES) return;
    int s = __ldg(&src[e]);
    int d = __ldg(&dst[e]);
    float2 ssv = *(const float2*)&g_ss[2 * s];
    float2 sdv = *(const float2*)&g_sd[2 * d];
    float ex0 = expf(leaky(ssv.x + sdv.x));
    float ex1 = expf(leaky(ssv.y + sdv.y));
    red_add_v2(&g_denom[2 * d], ex0, ex1);
}

// ---------------- GAT aggregation (head-mean folded, fp16 h2 gather) ---------
__global__ void k_gat_self() {
    int t = blockIdx.x * blockDim.x + threadIdx.x;
    if (t >= N_NODES * 16) return;
    int n = t >> 4, q = t & 15;
    float2 ssv = *(const float2*)&g_ss[2 * n];
    float2 sdv = *(const float2*)&g_sd[2 * n];
    float2 dn  = *(const float2*)&g_denom[2 * n];
    float c0 = 0.5f * expf(leaky(ssv.x + sdv.x)) / fmaxf(dn.x, 1e-16f);
    float c1 = 0.5f * expf(leaky(ssv.y + sdv.y)) / fmaxf(dn.y, 1e-16f);
    uint4 u = *(const uint4*)&g_h2x[(size_t)n * 64 + q * 4];
    float2 f0 = __half22float2(*(__half2*)&u.x);
    float2 f1 = __half22float2(*(__half2*)&u.y);
    float2 f2 = __half22float2(*(__half2*)&u.z);
    float2 f3 = __half22float2(*(__half2*)&u.w);
    *(float4*)&g_out_acc[(size_t)n * 64 + q * 4] =
        make_float4(c0 * f0.x + c1 * f0.y, c0 * f1.x + c1 * f1.y,
                    c0 * f2.x + c1 * f2.y, c0 * f3.x + c1 * f3.y);
}

__global__ void k_gat_edges(const int* __restrict__ src, const int* __restrict__ dst) {
    int g = blockIdx.x * blockDim.x + threadIdx.x;
    int e = g >> 4;
    if (e >= E_EDGES) return;
    int t = threadIdx.x & 15;
    int s = __ldg(&src[e]);
    int d = __ldg(&dst[e]);
    float c0 = 0.f, c1 = 0.f;
    if (t == 0) {
        float2 ssv = *(const float2*)&g_ss[2 * s];
        float2 sdv = *(const float2*)&g_sd[2 * d];
        float2 dn  = *(const float2*)&g_denom[2 * d];
        c0 = 0.5f * expf(leaky(ssv.x + sdv.x)) / fmaxf(dn.x, 1e-16f);
        c1 = 0.5f * expf(leaky(ssv.y + sdv.y)) / fmaxf(dn.y, 1e-16f);
    }
    c0 = __shfl_sync(0xffffffffu, c0, 0, 16);
    c1 = __shfl_sync(0xffffffffu, c1, 0, 16);
    uint4 u = *(const uint4*)&g_h2x[(size_t)s * 64 + t * 4];
    float2 f0 = __half22float2(*(__half2*)&u.x);
    float2 f1 = __half22float2(*(__half2*)&u.y);
    float2 f2 = __half22float2(*(__half2*)&u.z);
    float2 f3 = __half22float2(*(__half2*)&u.w);
    red_add_v4(&g_out_acc[(size_t)d * 64 + t * 4],
               make_float4(c0 * f0.x + c1 * f0.y, c0 * f1.x + c1 * f1.y,
                           c0 * f2.x + c1 * f2.y, c0 * f3.x + c1 * f3.y));
}

__global__ void k_final(const float* __restrict__ b, float* __restrict__ out) {
    int t = blockIdx.x * blockDim.x + threadIdx.x;
    if (t >= N_NODES * 16) return;
    int q = t & 15;
    float4 a = *(const float4*)&g_out_acc[(size_t)t * 4];
    float4 bv = *(const float4*)&b[q * 4];
    *(float4*)&out[(size_t)t * 4] =
        make_float4(fmaxf(a.x + bv.x, 0.f), fmaxf(a.y + bv.y, 0.f),
                    fmaxf(a.z + bv.z, 0.f), fmaxf(a.w + bv.w, 0.f));
}

// ---------------- launch -----------------------------------------------------
extern "C" void kernel_launch(void* const* d_in, const int* in_sizes, int n_in,
                              void* d_out, int out_size) {
    const float* x       = (const float*)d_in[0];
    const int*   ei      = (const int*)d_in[1];
    const float* ew      = (const float*)d_in[2];
    const float* gcn_w   = (const float*)d_in[3];
    const float* gcn_b   = (const float*)d_in[4];
    const float* gat_w   = (const float*)d_in[5];
    const float* att_src = (const float*)d_in[6];
    const float* att_dst = (const float*)d_in[7];
    const float* gat_b   = (const float*)d_in[8];
    float* out = (float*)d_out;
    const int* src = ei;
    const int* dst = ei + E_EDGES;

    const int B = 256;
    // degrees / normalization (needed by gemm1 epilogue)
    k_deg_init<<<(N_NODES + B - 1) / B, B>>>();
    k_deg_edges<<<(E_EDGES + B - 1) / B, B>>>(dst, ew);
    k_dinv<<<(N_NODES + B - 1) / B, B>>>();
    // GCN
    k_gemm1<<<(N_NODES + 127) / 128, B>>>(x, gcn_w);
    k_gcn_edges<<<(E_EDGES * 16 + B - 1) / B, B>>>(src, dst, ew);
    // GAT (gemm2 folds gcn bias+relu on staged input load)
    k_gemm2<<<(N_NODES + 63) / 64, B>>>(gat_w, att_src, att_dst, gcn_b);
    k_denom_edges<<<(E_EDGES + B - 1) / B, B>>>(src, dst);
    k_gat_self<<<(N_NODES * 16 + B - 1) / B, B>>>();
    k_gat_edges<<<(E_EDGES * 16 + B - 1) / B, B>>>(src, dst);
    k_final<<<(N_NODES * 16 + B - 1) / B, B>>>(gat_b, out);
}

// round 11
// speedup vs baseline: 1.5601x; 1.2493x over previous
#include <cuda_runtime.h>
#include <cuda_fp16.h>
#include <math.h>

#define N_NODES 100000
#define E_EDGES 1600000
#define NB_SCAN 98            // ceil(100000/1024)
// HID = 64, IN = 128, HEADS = 2

// ---------------- scratch (device globals; no allocations allowed) ----------
__device__ float   g_dinv[N_NODES];            // weighted deg -> dinv (in place)
__device__ int     g_cnt[N_NODES];             // in-edge count (no self)
__device__ int     g_off[N_NODES];             // CSR offsets (exclusive scan)
__device__ int     g_cur[N_NODES];             // scatter cursors
__device__ int     g_bsum[128];                // scan block sums
__device__ int     g_esrc[E_EDGES];            // CSR: src per slot
__device__ float   g_ew2[E_EDGES];             // CSR: edge weight per slot
__device__ float   g_h[N_NODES * 64];          // x @ gcn_w
__device__ float   g_acc[N_NODES * 64];        // GCN output (pre-bias/relu)
__device__ __half2 g_h2x[N_NODES * 64];        // h2 packed (head0,head1) per col
__device__ float   g_ss[N_NODES * 2];          // score_src per (node, head)
__device__ float   g_sd[N_NODES * 2];          // score_dst per (node, head)

// ---------------- helpers ----------------------------------------------------
__device__ __forceinline__ float leaky(float a) {
    return a >= 0.f ? a : 0.2f * a;
}

// ---------------- degree / count / norm --------------------------------------
__global__ void k_deg_init() {
    int t = blockIdx.x * blockDim.x + threadIdx.x;
    if (t < N_NODES) { g_dinv[t] = 1.0f; g_cnt[t] = 0; }   // self-loop weight 1
}
__global__ void k_deg_edges(const int* __restrict__ dst, const float* __restrict__ ew) {
    int e = blockIdx.x * blockDim.x + threadIdx.x;
    if (e < E_EDGES) {
        int d = dst[e];
        atomicAdd(&g_dinv[d], ew[e]);
        atomicAdd(&g_cnt[d], 1);
    }
}
__global__ void k_dinv() {
    int t = blockIdx.x * blockDim.x + threadIdx.x;
    if (t < N_NODES) g_dinv[t] = rsqrtf(g_dinv[t]);   // deg >= 1 always
}

// ---------------- CSR build: scan + scatter -----------------------------------
__global__ void k_scan1() {        // per-block exclusive scan of g_cnt
    __shared__ int sh[1024];
    int i = blockIdx.x * 1024 + threadIdx.x;
    int v = (i < N_NODES) ? g_cnt[i] : 0;
    sh[threadIdx.x] = v;
    __syncthreads();
#pragma unroll
    for (int off = 1; off < 1024; off <<= 1) {
        int t = (threadIdx.x >= off) ? sh[threadIdx.x - off] : 0;
        __syncthreads();
        sh[threadIdx.x] += t;
        __syncthreads();
    }
    if (i < N_NODES) g_off[i] = sh[threadIdx.x] - v;   // exclusive
    if (threadIdx.x == 1023) g_bsum[blockIdx.x] = sh[1023];
}
__global__ void k_scan2() {        // serial scan of 98 block sums
    if (threadIdx.x == 0) {
        int run = 0;
        for (int b = 0; b < NB_SCAN; b++) { int v = g_bsum[b]; g_bsum[b] = run; run += v; }
    }
}
__global__ void k_scan3() {        // add block base; init cursors
    int i = blockIdx.x * blockDim.x + threadIdx.x;
    if (i < N_NODES) {
        int o = g_off[i] + g_bsum[i >> 10];
        g_off[i] = o;
        g_cur[i] = o;
    }
}
__global__ void k_scatter(const int* __restrict__ src, const int* __restrict__ dst,
                          const float* __restrict__ ew) {
    int e = blockIdx.x * blockDim.x + threadIdx.x;
    if (e >= E_EDGES) return;
    int d = dst[e];
    int pos = atomicAdd(&g_cur[d], 1);
    g_esrc[pos] = src[e];
    g_ew2[pos] = ew[e];
}

// ---------------- GEMM1: g_h = x[N,128] @ gcn_w[128,64] ----------------------
// 4 nodes x 8 cols/thread; X staged through smem (R9 layout, proven).
__global__ void k_gemm1(const float* __restrict__ x, const float* __restrict__ W) {
    __shared__ float Ws[128 * 64];     // 32 KB row-major
    __shared__ float Xs[128 * 17];     // 8.7 KB (16-col chunks)
    int tid = threadIdx.x;
    for (int i = tid * 4; i < 128 * 64; i += 256 * 4)
        *(float4*)&Ws[i] = __ldg((const float4*)&W[i]);

    int cg = tid & 7;
    int ng = tid >> 3;                 // 0..31
    int n0 = blockIdx.x * 128 + ng * 4;

    float acc[4][8];
#pragma unroll
    for (int i = 0; i < 4; i++)
#pragma unroll
        for (int j = 0; j < 8; j++) acc[i][j] = 0.f;

#pragma unroll 1
    for (int kc = 0; kc < 8; kc++) {
        __syncthreads();
#pragma unroll
        for (int it = 0; it < 2; it++) {
            int g = it * 256 + tid;
            int n = g >> 2, c4 = g & 3;
            int gn = blockIdx.x * 128 + n;
            if (gn >= N_NODES) gn = N_NODES - 1;
            float4 v = __ldg((const float4*)&x[(size_t)gn * 128 + kc * 16 + c4 * 4]);
            float* dp = &Xs[n * 17 + c4 * 4];
            dp[0] = v.x; dp[1] = v.y; dp[2] = v.z; dp[3] = v.w;
        }
        __syncthreads();
#pragma unroll 1
        for (int k = 0; k < 16; k++) {
            int kk = kc * 16 + k;
            float4 wa = *(const float4*)&Ws[kk * 64 + cg * 4];
            float4 wb = *(const float4*)&Ws[kk * 64 + 32 + cg * 4];
            float xs0 = Xs[(ng * 4 + 0) * 17 + k];
            float xs1 = Xs[(ng * 4 + 1) * 17 + k];
            float xs2 = Xs[(ng * 4 + 2) * 17 + k];
            float xs3 = Xs[(ng * 4 + 3) * 17 + k];
#pragma unroll
            for (int i = 0; i < 4; i++) {
                float xs = (i == 0) ? xs0 : (i == 1) ? xs1 : (i == 2) ? xs2 : xs3;
                acc[i][0] += xs * wa.x; acc[i][1] += xs * wa.y;
                acc[i][2] += xs * wa.z; acc[i][3] += xs * wa.w;
                acc[i][4] += xs * wb.x; acc[i][5] += xs * wb.y;
                acc[i][6] += xs * wb.z; acc[i][7] += xs * wb.w;
            }
        }
    }
#pragma unroll
    for (int i = 0; i < 4; i++) {
        int n = n0 + i;
        if (n >= N_NODES) break;
        float* hout = &g_h[(size_t)n * 64];
        *(float4*)&hout[cg * 4]      = make_float4(acc[i][0], acc[i][1], acc[i][2], acc[i][3]);
        *(float4*)&hout[32 + cg * 4] = make_float4(acc[i][4], acc[i][5], acc[i][6], acc[i][7]);
    }
}

// ---------------- GCN aggregation over CSR (no atomics) ----------------------
// 16 lanes per node; edges in groups of 16; half-masked shfl broadcast.
__global__ void k_gcn_agg() {
    int gt = blockIdx.x * blockDim.x + threadIdx.x;
    int n = gt >> 4;
    if (n >= N_NODES) return;
    int t = threadIdx.x & 15;
    unsigned hm = 0xFFFFu << (threadIdx.x & 16);
    float dn = g_dinv[n];
    float c = dn * dn;
    float4 h = *(const float4*)&g_h[(size_t)n * 64 + t * 4];
    float4 a = make_float4(c * h.x, c * h.y, c * h.z, c * h.w);   // self term
    int beg = g_off[n];
    int end = beg + g_cnt[n];
    for (int j = beg; j < end; j += 16) {
        int e = j + t;
        int s = 0; float nrm = 0.f;
        if (e < end) {
            s = __ldg(&g_esrc[e]);
            nrm = g_dinv[s] * __ldg(&g_ew2[e]) * dn;
        }
        int cnt = min(16, end - j);
        for (int k = 0; k < cnt; k++) {
            int sk   = __shfl_sync(hm, s, k, 16);
            float nk = __shfl_sync(hm, nrm, k, 16);
            float4 hh = *(const float4*)&g_h[(size_t)sk * 64 + t * 4];
            a.x += nk * hh.x; a.y += nk * hh.y;
            a.z += nk * hh.z; a.w += nk * hh.w;
        }
    }
    *(float4*)&g_acc[(size_t)n * 64 + t * 4] = a;
}

// ---------------- GEMM2: h2 = relu(g_acc + gcn_b) @ gat_w[64,128] ------------
// 4 nodes x 8 cols/thread; packs __half2(h0,h1); scores via shfl. (R9 layout.)
__global__ void k_gemm2(const float* __restrict__ W, const float* __restrict__ as_,
                        const float* __restrict__ ad_, const float* __restrict__ gb) {
    __shared__ float Ws[64 * 128];    // 32 KB row-major
    __shared__ float Xs[64 * 33];     // 8.4 KB (32-col chunks)
    int tid = threadIdx.x;
    for (int i = tid * 4; i < 64 * 128; i += 256 * 4)
        *(float4*)&Ws[i] = __ldg((const float4*)&W[i]);

    int cg = tid & 15;
    int ng = tid >> 4;                 // 0..15
    int n0 = blockIdx.x * 64 + ng * 4;

    float acc[4][8];
#pragma unroll
    for (int i = 0; i < 4; i++)
#pragma unroll
        for (int j = 0; j < 8; j++) acc[i][j] = 0.f;

#pragma unroll 1
    for (int kc = 0; kc < 2; kc++) {
        __syncthreads();
#pragma unroll
        for (int it = 0; it < 2; it++) {
            int g = it * 256 + tid;
            int n = g >> 3, c4 = g & 7;
            int gn = blockIdx.x * 64 + n;
            if (gn >= N_NODES) gn = N_NODES - 1;
            float4 raw = __ldg((const float4*)&g_acc[(size_t)gn * 64 + kc * 32 + c4 * 4]);
            float4 bv = __ldg((const float4*)&gb[kc * 32 + c4 * 4]);
            float* dp = &Xs[n * 33 + c4 * 4];
            dp[0] = fmaxf(raw.x + bv.x, 0.f);
            dp[1] = fmaxf(raw.y + bv.y, 0.f);
            dp[2] = fmaxf(raw.z + bv.z, 0.f);
            dp[3] = fmaxf(raw.w + bv.w, 0.f);
        }
        __syncthreads();
#pragma unroll 1
        for (int k = 0; k < 32; k++) {
            int kk = kc * 32 + k;
            float4 wa = *(const float4*)&Ws[kk * 128 + cg * 4];       // head0
            float4 wb = *(const float4*)&Ws[kk * 128 + 64 + cg * 4];  // head1
            float xs0 = Xs[(ng * 4 + 0) * 33 + k];
            float xs1 = Xs[(ng * 4 + 1) * 33 + k];
            float xs2 = Xs[(ng * 4 + 2) * 33 + k];
            float xs3 = Xs[(ng * 4 + 3) * 33 + k];
#pragma unroll
            for (int i = 0; i < 4; i++) {
                float xs = (i == 0) ? xs0 : (i == 1) ? xs1 : (i == 2) ? xs2 : xs3;
                acc[i][0] += xs * wa.x; acc[i][1] += xs * wa.y;
                acc[i][2] += xs * wa.z; acc[i][3] += xs * wa.w;
                acc[i][4] += xs * wb.x; acc[i][5] += xs * wb.y;
                acc[i][6] += xs * wb.z; acc[i][7] += xs * wb.w;
            }
        }
    }
    float4 a0 = __ldg((const float4*)&as_[cg * 4]);
    float4 a1 = __ldg((const float4*)&as_[64 + cg * 4]);
    float4 d0 = __ldg((const float4*)&ad_[cg * 4]);
    float4 d1 = __ldg((const float4*)&ad_[64 + cg * 4]);
#pragma unroll
    for (int i = 0; i < 4; i++) {
        int n = n0 + i;
        bool valid = n < N_NODES;
        if (valid) {
            __half2 p0 = __floats2half2_rn(acc[i][0], acc[i][4]);
            __half2 p1 = __floats2half2_rn(acc[i][1], acc[i][5]);
            __half2 p2 = __floats2half2_rn(acc[i][2], acc[i][6]);
            __half2 p3 = __floats2half2_rn(acc[i][3], acc[i][7]);
            uint4 pk;
            pk.x = *(unsigned*)&p0; pk.y = *(unsigned*)&p1;
            pk.z = *(unsigned*)&p2; pk.w = *(unsigned*)&p3;
            *(uint4*)&g_h2x[(size_t)n * 64 + cg * 4] = pk;
        }
        float ps0 = acc[i][0] * a0.x + acc[i][1] * a0.y + acc[i][2] * a0.z + acc[i][3] * a0.w;
        float pd0 = acc[i][0] * d0.x + acc[i][1] * d0.y + acc[i][2] * d0.z + acc[i][3] * d0.w;
        float ps1 = acc[i][4] * a1.x + acc[i][5] * a1.y + acc[i][6] * a1.z + acc[i][7] * a1.w;
        float pd1 = acc[i][4] * d1.x + acc[i][5] * d1.y + acc[i][6] * d1.z + acc[i][7] * d1.w;
#pragma unroll
        for (int off = 1; off < 16; off <<= 1) {
            ps0 += __shfl_xor_sync(0xffffffffu, ps0, off, 16);
            pd0 += __shfl_xor_sync(0xffffffffu, pd0, off, 16);
            ps1 += __shfl_xor_sync(0xffffffffu, ps1, off, 16);
            pd1 += __shfl_xor_sync(0xffffffffu, pd1, off, 16);
        }
        if (cg == 0 && valid) {
            *(float2*)&g_ss[2 * n] = make_float2(ps0, ps1);
            *(float2*)&g_sd[2 * n] = make_float2(pd0, pd1);
        }
    }
}

// ---------------- GAT aggregation over CSR: softmax + mean + bias + relu -----
// Unnormalized numerators + denominator accumulated in ONE loop; divide at end.
__global__ void k_gat_agg(const float* __restrict__ b, float* __restrict__ out) {
    int gt = blockIdx.x * blockDim.x + threadIdx.x;
    int n = gt >> 4;
    if (n >= N_NODES) return;
    int t = threadIdx.x & 15;
    unsigned hm = 0xFFFFu << (threadIdx.x & 16);
    float2 sdv = *(const float2*)&g_sd[2 * n];
    float2 ssn = *(const float2*)&g_ss[2 * n];
    float selfex0 = expf(leaky(ssn.x + sdv.x));
    float selfex1 = expf(leaky(ssn.y + sdv.y));
    uint4 u = *(const uint4*)&g_h2x[(size_t)n * 64 + t * 4];
    float2 f0 = __half22float2(*(__half2*)&u.x);
    float2 f1 = __half22float2(*(__half2*)&u.y);
    float2 f2 = __half22float2(*(__half2*)&u.z);
    float2 f3 = __half22float2(*(__half2*)&u.w);
    float num0[4] = { selfex0 * f0.x, selfex0 * f1.x, selfex0 * f2.x, selfex0 * f3.x };
    float num1[4] = { selfex1 * f0.y, selfex1 * f1.y, selfex1 * f2.y, selfex1 * f3.y };
    float den0 = 0.f, den1 = 0.f;      // edge part; self added post-reduce
    int beg = g_off[n];
    int end = beg + g_cnt[n];
    for (int j = beg; j < end; j += 16) {
        int e = j + t;
        int s = 0; float ex0 = 0.f, ex1 = 0.f;
        if (e < end) {
            s = __ldg(&g_esrc[e]);
            float2 ssv = *(const float2*)&g_ss[2 * s];
            ex0 = expf(leaky(ssv.x + sdv.x));
            ex1 = expf(leaky(ssv.y + sdv.y));
        }
        den0 += ex0; den1 += ex1;
        int cnt = min(16, end - j);
        for (int k = 0; k < cnt; k++) {
            int sk   = __shfl_sync(hm, s, k, 16);
            float c0 = __shfl_sync(hm, ex0, k, 16);
            float c1 = __shfl_sync(hm, ex1, k, 16);
            uint4 uu = *(const uint4*)&g_h2x[(size_t)sk * 64 + t * 4];
            float2 e0 = __half22float2(*(__half2*)&uu.x);
            float2 e1 = __half22float2(*(__half2*)&uu.y);
            float2 e2 = __half22float2(*(__half2*)&uu.z);
            float2 e3 = __half22float2(*(__half2*)&uu.w);
            num0[0] += c0 * e0.x; num1[0] += c1 * e0.y;
            num0[1] += c0 * e1.x; num1[1] += c1 * e1.y;
            num0[2] += c0 * e2.x; num1[2] += c1 * e2.y;
            num0[3] += c0 * e3.x; num1[3] += c1 * e3.y;
        }
    }
#pragma unroll
    for (int off = 1; off < 16; off <<= 1) {
        den0 += __shfl_xor_sync(hm, den0, off, 16);
        den1 += __shfl_xor_sync(hm, den1, off, 16);
    }
    den0 += selfex0;   // every lane computed identical self terms
    den1 += selfex1;
    float r0 = 0.5f / fmaxf(den0, 1e-16f);
    float r1 = 0.5f / fmaxf(den1, 1e-16f);
    float4 bv = __ldg((const float4*)&b[t * 4]);
    *(float4*)&out[(size_t)n * 64 + t * 4] =
        make_float4(fmaxf(num0[0] * r0 + num1[0] * r1 + bv.x, 0.f),
                    fmaxf(num0[1] * r0 + num1[1] * r1 + bv.y, 0.f),
                    fmaxf(num0[2] * r0 + num1[2] * r1 + bv.z, 0.f),
                    fmaxf(num0[3] * r0 + num1[3] * r1 + bv.w, 0.f));
}

// ---------------- launch -----------------------------------------------------
extern "C" void kernel_launch(void* const* d_in, const int* in_sizes, int n_in,
                              void* d_out, int out_size) {
    const float* x       = (const float*)d_in[0];
    const int*   ei      = (const int*)d_in[1];
    const float* ew      = (const float*)d_in[2];
    const float* gcn_w   = (const float*)d_in[3];
    const float* gcn_b   = (const float*)d_in[4];
    const float* gat_w   = (const float*)d_in[5];
    const float* att_src = (const float*)d_in[6];
    const float* att_dst = (const float*)d_in[7];
    const float* gat_b   = (const float*)d_in[8];
    float* out = (float*)d_out;
    const int* src = ei;
    const int* dst = ei + E_EDGES;

    const int B = 256;
    // degrees + counts
    k_deg_init<<<(N_NODES + B - 1) / B, B>>>();
    k_deg_edges<<<(E_EDGES + B - 1) / B, B>>>(dst, ew);
    k_dinv<<<(N_NODES + B - 1) / B, B>>>();
    // CSR build
    k_scan1<<<NB_SCAN, 1024>>>();
    k_scan2<<<1, 32>>>();
    k_scan3<<<(N_NODES + B - 1) / B, B>>>();
    k_scatter<<<(E_EDGES + B - 1) / B, B>>>(src, dst, ew);
    // GCN
    k_gemm1<<<(N_NODES + 127) / 128, B>>>(x, gcn_w);
    k_gcn_agg<<<(N_NODES * 16 + B - 1) / B, B>>>();
    // GAT
    k_gemm2<<<(N_NODES + 63) / 64, B>>>(gat_w, att_src, att_dst, gcn_b);
    k_gat_agg<<<(N_NODES * 16 + B - 1) / B, B>>>(gat_b, out);
}

// round 13
// speedup vs baseline: 1.7931x; 1.1493x over previous
#include <cuda_runtime.h>
#include <cuda_fp16.h>
#include <math.h>

#define N_NODES 100000
#define E_EDGES 1600000
#define NB_SCAN 98            // ceil(100000/1024)
// HID = 64, IN = 128, HEADS = 2

// ---------------- scratch (device globals; no allocations allowed) ----------
__device__ float   g_dinv[N_NODES];            // weighted deg -> dinv (in place)
__device__ int     g_cnt[N_NODES];             // in-edge count (no self)
__device__ int     g_off[N_NODES];             // CSR offsets (exclusive scan)
__device__ int     g_cur[N_NODES];             // scatter cursors
__device__ int     g_bsum[128];                // scan block sums
__device__ int2    g_epack[E_EDGES];           // CSR: (src, ew bits) per slot
__device__ __half2 g_hh[N_NODES * 32];         // h (x@gcn_w) packed fp16 pairs
__device__ float   g_acc[N_NODES * 64];        // GCN output (pre-bias/relu)
__device__ __half2 g_h2x[N_NODES * 64];        // h2 packed (head0,head1) per col
__device__ float   g_ss[N_NODES * 2];          // score_src per (node, head)
__device__ float   g_sd[N_NODES * 2];          // score_dst per (node, head)

// ---------------- helpers ----------------------------------------------------
__device__ __forceinline__ float leaky(float a) {
    return a >= 0.f ? a : 0.2f * a;
}

// ---------------- degree / count ----------------------------------------------
__global__ void k_deg_init() {
    int t = blockIdx.x * blockDim.x + threadIdx.x;
    if (t < N_NODES) { g_dinv[t] = 1.0f; g_cnt[t] = 0; }   // self-loop weight 1
}
__global__ void k_deg_edges(const int* __restrict__ dst, const float* __restrict__ ew) {
    int e = blockIdx.x * blockDim.x + threadIdx.x;
    if (e < E_EDGES) {
        int d = dst[e];
        atomicAdd(&g_dinv[d], ew[e]);
        atomicAdd(&g_cnt[d], 1);
    }
}

// ---------------- CSR build: scan + scatter -----------------------------------
__global__ void k_scan1() {        // per-block exclusive scan of g_cnt
    __shared__ int sh[1024];
    int i = blockIdx.x * 1024 + threadIdx.x;
    int v = (i < N_NODES) ? g_cnt[i] : 0;
    sh[threadIdx.x] = v;
    __syncthreads();
#pragma unroll
    for (int off = 1; off < 1024; off <<= 1) {
        int t = (threadIdx.x >= off) ? sh[threadIdx.x - off] : 0;
        __syncthreads();
        sh[threadIdx.x] += t;
        __syncthreads();
    }
    if (i < N_NODES) g_off[i] = sh[threadIdx.x] - v;   // exclusive
    if (threadIdx.x == 1023) g_bsum[blockIdx.x] = sh[1023];
}
__global__ void k_scan2() {        // serial scan of 98 block sums
    if (threadIdx.x == 0) {
        int run = 0;
        for (int b = 0; b < NB_SCAN; b++) { int v = g_bsum[b]; g_bsum[b] = run; run += v; }
    }
}
__global__ void k_scan3() {        // add block base; init cursors; dinv fold
    int i = blockIdx.x * blockDim.x + threadIdx.x;
    if (i < N_NODES) {
        int o = g_off[i] + g_bsum[i >> 10];
        g_off[i] = o;
        g_cur[i] = o;
        g_dinv[i] = rsqrtf(g_dinv[i]);   // deg >= 1 always
    }
}
__global__ void k_scatter(const int* __restrict__ src, const int* __restrict__ dst,
                          const float* __restrict__ ew) {
    int e = blockIdx.x * blockDim.x + threadIdx.x;
    if (e >= E_EDGES) return;
    int d = dst[e];
    int pos = atomicAdd(&g_cur[d], 1);
    g_epack[pos] = make_int2(src[e], __float_as_int(ew[e]));
}

// ---------------- GEMM1: h = x[N,128] @ gcn_w[128,64] -> fp16 packed ---------
// 4 nodes x 8 cols/thread; X staged through smem (R9 layout, proven).
__global__ void k_gemm1(const float* __restrict__ x, const float* __restrict__ W) {
    __shared__ float Ws[128 * 64];     // 32 KB row-major
    __shared__ float Xs[128 * 17];     // 8.7 KB (16-col chunks)
    int tid = threadIdx.x;
    for (int i = tid * 4; i < 128 * 64; i += 256 * 4)
        *(float4*)&Ws[i] = __ldg((const float4*)&W[i]);

    int cg = tid & 7;
    int ng = tid >> 3;                 // 0..31
    int n0 = blockIdx.x * 128 + ng * 4;

    float acc[4][8];
#pragma unroll
    for (int i = 0; i < 4; i++)
#pragma unroll
        for (int j = 0; j < 8; j++) acc[i][j] = 0.f;

#pragma unroll 1
    for (int kc = 0; kc < 8; kc++) {
        __syncthreads();
#pragma unroll
        for (int it = 0; it < 2; it++) {
            int g = it * 256 + tid;
            int n = g >> 2, c4 = g & 3;
            int gn = blockIdx.x * 128 + n;
            if (gn >= N_NODES) gn = N_NODES - 1;
            float4 v = __ldg((const float4*)&x[(size_t)gn * 128 + kc * 16 + c4 * 4]);
            float* dp = &Xs[n * 17 + c4 * 4];
            dp[0] = v.x; dp[1] = v.y; dp[2] = v.z; dp[3] = v.w;
        }
        __syncthreads();
#pragma unroll 1
        for (int k = 0; k < 16; k++) {
            int kk = kc * 16 + k;
            float4 wa = *(const float4*)&Ws[kk * 64 + cg * 4];
            float4 wb = *(const float4*)&Ws[kk * 64 + 32 + cg * 4];
            float xs0 = Xs[(ng * 4 + 0) * 17 + k];
            float xs1 = Xs[(ng * 4 + 1) * 17 + k];
            float xs2 = Xs[(ng * 4 + 2) * 17 + k];
            float xs3 = Xs[(ng * 4 + 3) * 17 + k];
#pragma unroll
            for (int i = 0; i < 4; i++) {
                float xs = (i == 0) ? xs0 : (i == 1) ? xs1 : (i == 2) ? xs2 : xs3;
                acc[i][0] += xs * wa.x; acc[i][1] += xs * wa.y;
                acc[i][2] += xs * wa.z; acc[i][3] += xs * wa.w;
                acc[i][4] += xs * wb.x; acc[i][5] += xs * wb.y;
                acc[i][6] += xs * wb.z; acc[i][7] += xs * wb.w;
            }
        }
    }
#pragma unroll
    for (int i = 0; i < 4; i++) {
        int n = n0 + i;
        if (n >= N_NODES) break;
        __half2 a01 = __floats2half2_rn(acc[i][0], acc[i][1]);
        __half2 a23 = __floats2half2_rn(acc[i][2], acc[i][3]);
        __half2 b01 = __floats2half2_rn(acc[i][4], acc[i][5]);
        __half2 b23 = __floats2half2_rn(acc[i][6], acc[i][7]);
        uint2 pa, pb;
        pa.x = *(unsigned*)&a01; pa.y = *(unsigned*)&a23;
        pb.x = *(unsigned*)&b01; pb.y = *(unsigned*)&b23;
        *(uint2*)&g_hh[(size_t)n * 32 + 2 * cg]      = pa;   // cols 4cg..4cg+3
        *(uint2*)&g_hh[(size_t)n * 32 + 16 + 2 * cg] = pb;   // cols 32+4cg..
    }
}

// ---------------- GCN aggregation over CSR (no atomics, fp16 gather) ---------
// 16 lanes per node; edges in groups of 16; half-masked shfl broadcast.
__global__ void k_gcn_agg() {
    int gt = blockIdx.x * blockDim.x + threadIdx.x;
    int n = gt >> 4;
    if (n >= N_NODES) return;
    int t = threadIdx.x & 15;
    unsigned hm = 0xFFFFu << (threadIdx.x & 16);
    float dn = g_dinv[n];
    float c = dn * dn;
    uint2 u = *(const uint2*)&g_hh[(size_t)n * 32 + 2 * t];
    float2 h01 = __half22float2(*(__half2*)&u.x);
    float2 h23 = __half22float2(*(__half2*)&u.y);
    float4 a = make_float4(c * h01.x, c * h01.y, c * h23.x, c * h23.y);   // self
    int beg = g_off[n];
    int end = beg + g_cnt[n];
    for (int j = beg; j < end; j += 16) {
        int e = j + t;
        int s = 0; float nrm = 0.f;
        if (e < end) {
            int2 p = __ldg(&g_epack[e]);
            s = p.x;
            nrm = g_dinv[s] * __int_as_float(p.y) * dn;
        }
        int cnt = min(16, end - j);
        for (int k = 0; k < cnt; k++) {
            int sk   = __shfl_sync(hm, s, k, 16);
            float nk = __shfl_sync(hm, nrm, k, 16);
            uint2 uu = *(const uint2*)&g_hh[(size_t)sk * 32 + 2 * t];
            float2 e01 = __half22float2(*(__half2*)&uu.x);
            float2 e23 = __half22float2(*(__half2*)&uu.y);
            a.x += nk * e01.x; a.y += nk * e01.y;
            a.z += nk * e23.x; a.w += nk * e23.y;
        }
    }
    *(float4*)&g_acc[(size_t)n * 64 + t * 4] = a;
}

// ---------------- GEMM2: h2 = relu(g_acc + gcn_b) @ gat_w[64,128] ------------
// 4 nodes x 8 cols/thread; packs __half2(h0,h1); scores via shfl. (R9 layout.)
__global__ void k_gemm2(const float* __restrict__ W, const float* __restrict__ as_,
                        const float* __restrict__ ad_, const float* __restrict__ gb) {
    __shared__ float Ws[64 * 128];    // 32 KB row-major
    __shared__ float Xs[64 * 33];     // 8.4 KB (32-col chunks)
    int tid = threadIdx.x;
    for (int i = tid * 4; i < 64 * 128; i += 256 * 4)
        *(float4*)&Ws[i] = __ldg((const float4*)&W[i]);

    int cg = tid & 15;
    int ng = tid >> 4;                 // 0..15
    int n0 = blockIdx.x * 64 + ng * 4;

    float acc[4][8];
#pragma unroll
    for (int i = 0; i < 4; i++)
#pragma unroll
        for (int j = 0; j < 8; j++) acc[i][j] = 0.f;

#pragma unroll 1
    for (int kc = 0; kc < 2; kc++) {
        __syncthreads();
#pragma unroll
        for (int it = 0; it < 2; it++) {
            int g = it * 256 + tid;
            int n = g >> 3, c4 = g & 7;
            int gn = blockIdx.x * 64 + n;
            if (gn >= N_NODES) gn = N_NODES - 1;
            float4 raw = __ldg((const float4*)&g_acc[(size_t)gn * 64 + kc * 32 + c4 * 4]);
            float4 bv = __ldg((const float4*)&gb[kc * 32 + c4 * 4]);
            float* dp = &Xs[n * 33 + c4 * 4];
            dp[0] = fmaxf(raw.x + bv.x, 0.f);
            dp[1] = fmaxf(raw.y + bv.y, 0.f);
            dp[2] = fmaxf(raw.z + bv.z, 0.f);
            dp[3] = fmaxf(raw.w + bv.w, 0.f);
        }
        __syncthreads();
#pragma unroll 1
        for (int k = 0; k < 32; k++) {
            int kk = kc * 32 + k;
            float4 wa = *(const float4*)&Ws[kk * 128 + cg * 4];       // head0
            float4 wb = *(const float4*)&Ws[kk * 128 + 64 + cg * 4];  // head1
            float xs0 = Xs[(ng * 4 + 0) * 33 + k];
            float xs1 = Xs[(ng * 4 + 1) * 33 + k];
            float xs2 = Xs[(ng * 4 + 2) * 33 + k];
            float xs3 = Xs[(ng * 4 + 3) * 33 + k];
#pragma unroll
            for (int i = 0; i < 4; i++) {
                float xs = (i == 0) ? xs0 : (i == 1) ? xs1 : (i == 2) ? xs2 : xs3;
                acc[i][0] += xs * wa.x; acc[i][1] += xs * wa.y;
                acc[i][2] += xs * wa.z; acc[i][3] += xs * wa.w;
                acc[i][4] += xs * wb.x; acc[i][5] += xs * wb.y;
                acc[i][6] += xs * wb.z; acc[i][7] += xs * wb.w;
            }
        }
    }
    float4 a0 = __ldg((const float4*)&as_[cg * 4]);
    float4 a1 = __ldg((const float4*)&as_[64 + cg * 4]);
    float4 d0 = __ldg((const float4*)&ad_[cg * 4]);
    float4 d1 = __ldg((const float4*)&ad_[64 + cg * 4]);
#pragma unroll
    for (int i = 0; i < 4; i++) {
        int n = n0 + i;
        bool valid = n < N_NODES;
        if (valid) {
            __half2 p0 = __floats2half2_rn(acc[i][0], acc[i][4]);
            __half2 p1 = __floats2half2_rn(acc[i][1], acc[i][5]);
            __half2 p2 = __floats2half2_rn(acc[i][2], acc[i][6]);
            __half2 p3 = __floats2half2_rn(acc[i][3], acc[i][7]);
            uint4 pk;
            pk.x = *(unsigned*)&p0; pk.y = *(unsigned*)&p1;
            pk.z = *(unsigned*)&p2; pk.w = *(unsigned*)&p3;
            *(uint4*)&g_h2x[(size_t)n * 64 + cg * 4] = pk;
        }
        float ps0 = acc[i][0] * a0.x + acc[i][1] * a0.y + acc[i][2] * a0.z + acc[i][3] * a0.w;
        float pd0 = acc[i][0] * d0.x + acc[i][1] * d0.y + acc[i][2] * d0.z + acc[i][3] * d0.w;
        float ps1 = acc[i][4] * a1.x + acc[i][5] * a1.y + acc[i][6] * a1.z + acc[i][7] * a1.w;
        float pd1 = acc[i][4] * d1.x + acc[i][5] * d1.y + acc[i][6] * d1.z + acc[i][7] * d1.w;
#pragma unroll
        for (int off = 1; off < 16; off <<= 1) {
            ps0 += __shfl_xor_sync(0xffffffffu, ps0, off, 16);
            pd0 += __shfl_xor_sync(0xffffffffu, pd0, off, 16);
            ps1 += __shfl_xor_sync(0xffffffffu, ps1, off, 16);
            pd1 += __shfl_xor_sync(0xffffffffu, pd1, off, 16);
        }
        if (cg == 0 && valid) {
            *(float2*)&g_ss[2 * n] = make_float2(ps0, ps1);
            *(float2*)&g_sd[2 * n] = make_float2(pd0, pd1);
        }
    }
}

// ---------------- GAT aggregation over CSR: softmax + mean + bias + relu -----
__global__ void k_gat_agg(const float* __restrict__ b, float* __restrict__ out) {
    int gt = blockIdx.x * blockDim.x + threadIdx.x;
    int n = gt >> 4;
    if (n >= N_NODES) return;
    int t = threadIdx.x & 15;
    unsigned hm = 0xFFFFu << (threadIdx.x & 16);
    float2 sdv = *(const float2*)&g_sd[2 * n];
    float2 ssn = *(const float2*)&g_ss[2 * n];
    float selfex0 = expf(leaky(ssn.x + sdv.x));
    float selfex1 = expf(leaky(ssn.y + sdv.y));
    uint4 u = *(const uint4*)&g_h2x[(size_t)n * 64 + t * 4];
    float2 f0 = __half22float2(*(__half2*)&u.x);
    float2 f1 = __half22float2(*(__half2*)&u.y);
    float2 f2 = __half22float2(*(__half2*)&u.z);
    float2 f3 = __half22float2(*(__half2*)&u.w);
    float num0[4] = { selfex0 * f0.x, selfex0 * f1.x, selfex0 * f2.x, selfex0 * f3.x };
    float num1[4] = { selfex1 * f0.y, selfex1 * f1.y, selfex1 * f2.y, selfex1 * f3.y };
    float den0 = 0.f, den1 = 0.f;      // edge part; self added post-reduce
    int beg = g_off[n];
    int end = beg + g_cnt[n];
    for (int j = beg; j < end; j += 16) {
        int e = j + t;
        int s = 0; float ex0 = 0.f, ex1 = 0.f;
        if (e < end) {
            s = __ldg(&g_epack[e]).x;
            float2 ssv = *(const float2*)&g_ss[2 * s];
            ex0 = expf(leaky(ssv.x + sdv.x));
            ex1 = expf(leaky(ssv.y + sdv.y));
        }
        den0 += ex0; den1 += ex1;
        int cnt = min(16, end - j);
        for (int k = 0; k < cnt; k++) {
            int sk   = __shfl_sync(hm, s, k, 16);
            float c0 = __shfl_sync(hm, ex0, k, 16);
            float c1 = __shfl_sync(hm, ex1, k, 16);
            uint4 uu = *(const uint4*)&g_h2x[(size_t)sk * 64 + t * 4];
            float2 e0 = __half22float2(*(__half2*)&uu.x);
            float2 e1 = __half22float2(*(__half2*)&uu.y);
            float2 e2 = __half22float2(*(__half2*)&uu.z);
            float2 e3 = __half22float2(*(__half2*)&uu.w);
            num0[0] += c0 * e0.x; num1[0] += c1 * e0.y;
            num0[1] += c0 * e1.x; num1[1] += c1 * e1.y;
            num0[2] += c0 * e2.x; num1[2] += c1 * e2.y;
            num0[3] += c0 * e3.x; num1[3] += c1 * e3.y;
        }
    }
#pragma unroll
    for (int off = 1; off < 16; off <<= 1) {
        den0 += __shfl_xor_sync(hm, den0, off, 16);
        den1 += __shfl_xor_sync(hm, den1, off, 16);
    }
    den0 += selfex0;   // every lane computed identical self terms
    den1 += selfex1;
    float r0 = 0.5f / fmaxf(den0, 1e-16f);
    float r1 = 0.5f / fmaxf(den1, 1e-16f);
    float4 bv = __ldg((const float4*)&b[t * 4]);
    *(float4*)&out[(size_t)n * 64 + t * 4] =
        make_float4(fmaxf(num0[0] * r0 + num1[0] * r1 + bv.x, 0.f),
                    fmaxf(num0[1] * r0 + num1[1] * r1 + bv.y, 0.f),
                    fmaxf(num0[2] * r0 + num1[2] * r1 + bv.z, 0.f),
                    fmaxf(num0[3] * r0 + num1[3] * r1 + bv.w, 0.f));
}

// ---------------- launch -----------------------------------------------------
static cudaStream_t g_s2 = 0;
static cudaEvent_t  g_evF = 0, g_evJ = 0;

extern "C" void kernel_launch(void* const* d_in, const int* in_sizes, int n_in,
                              void* d_out, int out_size) {
    const float* x       = (const float*)d_in[0];
    const int*   ei      = (const int*)d_in[1];
    const float* ew      = (const float*)d_in[2];
    const float* gcn_w   = (const float*)d_in[3];
    const float* gcn_b   = (const float*)d_in[4];
    const float* gat_w   = (const float*)d_in[5];
    const float* att_src = (const float*)d_in[6];
    const float* att_dst = (const float*)d_in[7];
    const float* gat_b   = (const float*)d_in[8];
    float* out = (float*)d_out;
    const int* src = ei;
    const int* dst = ei + E_EDGES;

    if (!g_s2) {   // first call is the (uncaptured) correctness run
        cudaStreamCreateWithFlags(&g_s2, cudaStreamNonBlocking);
        cudaEventCreateWithFlags(&g_evF, cudaEventDisableTiming);
        cudaEventCreateWithFlags(&g_evJ, cudaEventDisableTiming);
    }

    const int B = 256;
    // fork: degree + CSR build on stream 2, overlapped with gemm1
    cudaEventRecord(g_evF, 0);
    cudaStreamWaitEvent(g_s2, g_evF, 0);
    k_deg_init<<<(N_NODES + B - 1) / B, B, 0, g_s2>>>();
    k_deg_edges<<<(E_EDGES + B - 1) / B, B, 0, g_s2>>>(dst, ew);
    k_scan1<<<NB_SCAN, 1024, 0, g_s2>>>();
    k_scan2<<<1, 32, 0, g_s2>>>();
    k_scan3<<<(N_NODES + B - 1) / B, B, 0, g_s2>>>();
    k_scatter<<<(E_EDGES + B - 1) / B, B, 0, g_s2>>>(src, dst, ew);
    cudaEventRecord(g_evJ, g_s2);

    // main stream: gemm1 (depends only on x, W)
    k_gemm1<<<(N_NODES + 127) / 128, B>>>(x, gcn_w);

    // join, then the dependent chain
    cudaStreamWaitEvent(0, g_evJ, 0);
    k_gcn_agg<<<(N_NODES * 16 + B - 1) / B, B>>>();
    k_gemm2<<<(N_NODES + 63) / 64, B>>>(gat_w, att_src, att_dst, gcn_b);
    k_gat_agg<<<(N_NODES * 16 + B - 1) / B, B>>>(gat_b, out);
}